// round 11
// baseline (speedup 1.0000x reference)
#include <cuda_runtime.h>
#include <cstdint>

#define SEQ   4096
#define TPB   128
#define HALF  2048                 // tokens per pipeline granule (8 KB)
#define RPC   4                    // rows per CTA
#define NG    (RPC * 2)            // granules per CTA
#define NW    (TPB / 32)

__device__ __forceinline__ unsigned prmt(unsigned a, unsigned b, unsigned sel) {
    unsigned r;
    asm("prmt.b32 %0, %1, %2, %3;" : "=r"(r) : "r"(a), "r"(b), "r"(sel));
    return r;
}

__device__ __forceinline__ unsigned smem_u32(const void* p) {
    unsigned r;
    asm("{ .reg .u64 t; cvta.to.shared.u64 t, %1; cvt.u32.u64 %0, t; }"
        : "=r"(r) : "l"(p));
    return r;
}

__device__ __forceinline__ void mbar_wait(unsigned mb, unsigned parity) {
    unsigned done;
    do {
        asm volatile(
            "{\n\t.reg .pred p;\n\t"
            "mbarrier.try_wait.parity.shared.b64 p, [%1], %2;\n\t"
            "selp.b32 %0, 1, 0, p;\n\t}"
            : "=r"(done) : "r"(mb), "r"(parity) : "memory");
    } while (!done);
}

// SWAR detect + resolve for 16 contiguous tokens (4 packed words). Verbatim
// logic from the validated kernel. rtag: -1 on entry (carry handled above).
__device__ __forceinline__ void batch16(const unsigned P[4], unsigned nfw, int qtag,
                                        int& rtag, unsigned& mL, unsigned& mC)
{
    unsigned N[4];
    N[0] = prmt(P[0], P[1], 0x4321);
    N[1] = prmt(P[1], P[2], 0x4321);
    N[2] = prmt(P[2], P[3], 0x4321);
    N[3] = prmt(P[3], nfw,  0x4321);

    unsigned tagpos = 0, candpos = 0;
    #pragma unroll
    for (int w = 0; w < 4; w++) {
        unsigned p = P[w], n = N[w];
        unsigned d1 = p + 0x52525252u;              // tag: (c-46) <u 3
        unsigned d2 = d1 - 0x03030303u;
        unsigned tm = (d1 & ~d2) & 0x80808080u;
        unsigned r1 = p + 0x7D7D7D7Du;              // role: (c-3) <u 3
        unsigned r2 = r1 - 0x03030303u;
        unsigned rm = (r1 & ~r2) & 0x80808080u;
        unsigned c8  = (p << 3) & 0xF8F8F8F8u;
        unsigned c8r = c8 & ((rm >> 7) * 0xF8u);    // mask junk-byte borrows
        unsigned e1 = (n + 0x82828282u) - c8r;      // (n+2-8c) >= 0
        unsigned e2 = e1 - 0x08080808u;             // (n+2-8c) >= 8
        unsigned cm = (e1 & ~e2) & rm;
        tagpos  |= ((tm * 0x00204081u) >> 28) << (4 * w);
        candpos |= ((cm * 0x00204081u) >> 28) << (4 * w);
    }

    while (candpos) {
        int k = __ffs(candpos) - 1;
        candpos &= candpos - 1;
        unsigned nw = (k & 8) ? ((k & 4) ? N[3] : N[2])
                              : ((k & 4) ? N[1] : N[0]);
        unsigned u  = (prmt(nw, 0u, (unsigned)(k & 3)) & 0xFFu) - 22u;
        unsigned bit = 1u << u;
        unsigned tb = tagpos & ((2u << k) - 1u);    // in-batch tags at pos <= k
        if (tb) {
            int j = 31 - __clz(tb);
            unsigned pw = (j & 8) ? ((j & 4) ? P[3] : P[2])
                                  : ((j & 4) ? P[1] : P[0]);
            int tv = (int)(prmt(pw, 0u, (unsigned)(j & 3)) & 0xFFu) - 46;
            if (tv == qtag) mL |= bit;
        } else if (rtag >= 0) {
            if (rtag == qtag) mL |= bit;
        } else {
            mC |= bit;                              // pending: resolved by outer carry
        }
    }

    if (tagpos) {
        int j = 31 - __clz(tagpos);
        unsigned pw = (j & 8) ? ((j & 4) ? P[3] : P[2])
                              : ((j & 4) ? P[1] : P[0]);
        rtag = (int)(prmt(pw, 0u, (unsigned)(j & 3)) & 0xFFu) - 46;
    }
}

__global__ __launch_bounds__(TPB)
void tlc_kernel(const int* __restrict__ tok,
                const float* __restrict__ table,
                float* __restrict__ out)
{
    const int tid  = threadIdx.x;
    const int lane = tid & 31;
    const int wid  = tid >> 5;
    const int r0   = blockIdx.x * RPC;
    const int* base = tok + (size_t)r0 * SEQ;       // 8 contiguous 8KB granules

    __shared__ alignas(16) unsigned sRaw[2][HALF];  // 2 x 8 KB TMA buffers
    __shared__ unsigned sTok[HALF / 4];             // 2 KB packed (reused per half)
    __shared__ alignas(8) unsigned long long mbar[2];
    __shared__ unsigned sM[NW], sP[NW];
    __shared__ int      sL[NW];
    __shared__ int      sQ;                         // row last token (for qtag)
    __shared__ int      sT;                         // row t[1] (task token)

    const unsigned mb0 = smem_u32(&mbar[0]);
    const unsigned mb1 = smem_u32(&mbar[1]);

    if (tid == 0) {
        asm volatile("mbarrier.init.shared.b64 [%0], %1;" :: "r"(mb0), "r"(1) : "memory");
        asm volatile("mbarrier.init.shared.b64 [%0], %1;" :: "r"(mb1), "r"(1) : "memory");
    }
    __syncthreads();
    if (tid == 0) {
        #pragma unroll
        for (int k = 0; k < 2; k++) {
            unsigned mb = k ? mb1 : mb0;
            asm volatile("mbarrier.arrive.expect_tx.shared.b64 _, [%0], %1;"
                         :: "r"(mb), "r"((unsigned)(HALF * 4)) : "memory");
            asm volatile(
                "cp.async.bulk.shared::cluster.global.mbarrier::complete_tx::bytes "
                "[%0], [%1], %2, [%3];"
                :: "r"(smem_u32(sRaw[k])), "l"(base + k * HALF),
                   "r"((unsigned)(HALF * 4)), "r"(mb)
                : "memory");
        }
    }

    int carry = -1;                  // row-running tag (thread 0 only)
    unsigned acc = 0;                // row-accumulated mask (thread 0 only)

    #pragma unroll 1
    for (int g = 0; g < NG; g++) {
        const int b = g & 1;
        const int h = g & 1;         // half within row == buffer parity here (NG even)
        const int* t = base + (size_t)(g >> 1) * SEQ;
        const unsigned mb = b ? mb1 : mb0;

        mbar_wait(mb, (unsigned)((g >> 1) & 1));

        if (h == 0 && tid == 0) {    // row prologue: uniform L2-resident loads
            sQ = __ldg(&t[SEQ - 1]);
            sT = __ldg(&t[1]);
        }

        // ---- restage: raw uint4 -> packed bytes (all accesses conflict-free)
        const uint4* raw4 = reinterpret_cast<const uint4*>(sRaw[b]);
        #pragma unroll
        for (int i = 0; i < 4; i++) {
            uint4 v = raw4[i * TPB + tid];
            unsigned lo = prmt(v.x, v.y, 0x0040);
            unsigned hi = prmt(v.z, v.w, 0x4000);
            sTok[i * TPB + tid] = prmt(lo, hi, 0x7610);
        }
        __syncthreads();             // packed ready; raw[b] fully consumed; sQ/sT visible

        // keep the copy engine busy: next granule into this buffer immediately
        if (tid == 0 && g + 2 < NG) {
            asm volatile("mbarrier.arrive.expect_tx.shared.b64 _, [%0], %1;"
                         :: "r"(mb), "r"((unsigned)(HALF * 4)) : "memory");
            asm volatile(
                "cp.async.bulk.shared::cluster.global.mbarrier::complete_tx::bytes "
                "[%0], [%1], %2, [%3];"
                :: "r"(smem_u32(sRaw[b])), "l"(base + (g + 2) * HALF),
                   "r"((unsigned)(HALF * 4)), "r"(mb)
                : "memory");
        }

        const int qtag = min(max(sQ - 46, 0), 2);

        // ---- my 16 contiguous tokens (LDS.128, 16B stride: conflict-free)
        unsigned P[4];
        *reinterpret_cast<uint4*>(P) = *reinterpret_cast<const uint4*>(&sTok[tid * 4]);
        unsigned nfw;
        if (tid < TPB - 1)      nfw = sTok[tid * 4 + 4];
        else if (h == 0)        nfw = (unsigned)__ldg(&t[HALF]);   // half boundary
        else                    nfw = 0u;                          // row end sentinel

        int rtag = -1;
        unsigned mL = 0, mC = 0;
        batch16(P, nfw, qtag, rtag, mL, mC);

        // ---- warp inclusive scan of rtag: combine(a,b) = (b>=0 ? b : a)
        int inc = rtag;
        #pragma unroll
        for (int off = 1; off < 32; off <<= 1) {
            int p = __shfl_up_sync(0xffffffffu, inc, off);
            if (lane >= off && inc < 0) inc = p;
        }
        int excl = __shfl_up_sync(0xffffffffu, inc, 1);
        if (lane == 0) excl = -1;

        unsigned m    = mL | ((excl == qtag) ? mC : 0u);
        unsigned pend = (excl < 0) ? mC : 0u;
        m    = __reduce_or_sync(0xffffffffu, m);
        pend = __reduce_or_sync(0xffffffffu, pend);
        const int wlast = __shfl_sync(0xffffffffu, inc, 31);

        if (lane == 0) { sM[wid] = m; sP[wid] = pend; sL[wid] = wlast; }
        __syncthreads();

        // ---- cross-warp resolve for this half (4 lanes); thread 0 carries the row
        if (tid < NW) {
            unsigned mm = sM[tid], pp = sP[tid];
            int c2 = sL[tid];
            #pragma unroll
            for (int off = 1; off < NW; off <<= 1) {
                int p = __shfl_up_sync(0xfu, c2, off);
                if (tid >= off && c2 < 0) c2 = p;
            }
            int ex = __shfl_up_sync(0xfu, c2, 1);
            if (tid == 0) ex = -1;
            unsigned res   = mm | ((ex == qtag) ? pp : 0u);
            unsigned pendh = (ex < 0) ? pp : 0u;          // needs row carry
            res   = __reduce_or_sync(0xfu, res);
            pendh = __reduce_or_sync(0xfu, pendh);
            const int blockLast = __shfl_sync(0xfu, c2, NW - 1);

            if (tid == 0) {
                acc |= res | ((carry == qtag) ? pendh : 0u);
                if (blockLast >= 0) carry = blockLast;

                if (h == 1) {                             // ---- row epilogue
                    unsigned mA  =  acc        & 0xffu;
                    unsigned mB  = (acc >> 8)  & 0xffu;
                    unsigned mCm = (acc >> 16) & 0xffu;
                    const int a = mA  ? (__ffs(mA)  - 1) : 0;
                    const int bb = mB  ? (__ffs(mB)  - 1) : 0;
                    const int c = mCm ? (__ffs(mCm) - 1) : 0;
                    const int task = min(max(sT - 49, 0), 3);

                    float o[8];
                    if (task == 3) {
                        const float* tp = table + (((a * 8 + bb) * 8 + c) * 8);
                        #pragma unroll
                        for (int k = 0; k < 8; k++) o[k] = __ldg(&tp[k]);
                    } else {
                        int idx;
                        if (task == 0)      idx = a;
                        else if (task == 1) idx = (a + 2 * bb + 3 * c) & 7;
                        else                idx = (a * (bb + 1) + c * ((a ^ bb) + 1)) & 7;
                        #pragma unroll
                        for (int k = 0; k < 8; k++) o[k] = (k == idx) ? 12.0f : 0.0f;
                    }
                    float4* o4 = reinterpret_cast<float4*>(out + (size_t)(r0 + (g >> 1)) * 8);
                    o4[0] = make_float4(o[0], o[1], o[2], o[3]);
                    o4[1] = make_float4(o[4], o[5], o[6], o[7]);

                    acc = 0; carry = -1;                  // reset for next row
                }
            }
        }
    }
}

extern "C" void kernel_launch(void* const* d_in, const int* in_sizes, int n_in,
                              void* d_out, int out_size)
{
    const int* tok     = (const int*)d_in[0];     // token_ids [B, 4096] int32
    const float* table = (const float*)d_in[1];   // lookup_table [8,8,8,8] f32
    float* out         = (float*)d_out;           // [B, 8] f32

    const int B = in_sizes[0] / SEQ;
    tlc_kernel<<<B / RPC, TPB>>>(tok, table, out);
}

// round 12
// speedup vs baseline: 1.1371x; 1.1371x over previous
#include <cuda_runtime.h>
#include <cstdint>

#define SEQ   4096
#define TPB   128
#define HALF  2048                 // tokens per TMA granule (8 KB)
#define NW    (TPB / 32)

__device__ __forceinline__ unsigned prmt(unsigned a, unsigned b, unsigned sel) {
    unsigned r;
    asm("prmt.b32 %0, %1, %2, %3;" : "=r"(r) : "r"(a), "r"(b), "r"(sel));
    return r;
}

// word-index swizzle: XOR bits[4:2] ^= bits[7:5]; staging STS (stride-1) and
// processing LDS.128 (stride-8 words) both conflict-free.
__device__ __forceinline__ unsigned swz(unsigned idx) {
    return idx ^ (((idx >> 5) & 7u) << 2);
}

__device__ __forceinline__ unsigned smem_u32(const void* p) {
    unsigned r;
    asm("{ .reg .u64 t; cvta.to.shared.u64 t, %1; cvt.u32.u64 %0, t; }"
        : "=r"(r) : "l"(p));
    return r;
}

__device__ __forceinline__ void mbar_wait(unsigned mb, unsigned parity) {
    unsigned done;
    do {
        asm volatile(
            "{\n\t.reg .pred p;\n\t"
            "mbarrier.try_wait.parity.shared.b64 p, [%1], %2;\n\t"
            "selp.b32 %0, 1, 0, p;\n\t}"
            : "=r"(done) : "r"(mb), "r"(parity) : "memory");
    } while (!done);
}

// SWAR detect + resolve for 16 contiguous tokens (4 packed words). Verbatim
// logic from the validated kernel (rel_err=0 across 6 rounds).
__device__ __forceinline__ void batch16(const unsigned P[4], unsigned nfw, int qtag,
                                        int& rtag, unsigned& mL, unsigned& mC)
{
    unsigned N[4];
    N[0] = prmt(P[0], P[1], 0x4321);
    N[1] = prmt(P[1], P[2], 0x4321);
    N[2] = prmt(P[2], P[3], 0x4321);
    N[3] = prmt(P[3], nfw,  0x4321);

    unsigned tagpos = 0, candpos = 0;
    #pragma unroll
    for (int w = 0; w < 4; w++) {
        unsigned p = P[w], n = N[w];
        unsigned d1 = p + 0x52525252u;              // tag: (c-46) <u 3
        unsigned d2 = d1 - 0x03030303u;
        unsigned tm = (d1 & ~d2) & 0x80808080u;
        unsigned r1 = p + 0x7D7D7D7Du;              // role: (c-3) <u 3
        unsigned r2 = r1 - 0x03030303u;
        unsigned rm = (r1 & ~r2) & 0x80808080u;
        unsigned c8  = (p << 3) & 0xF8F8F8F8u;
        unsigned c8r = c8 & ((rm >> 7) * 0xF8u);    // mask junk-byte borrows
        unsigned e1 = (n + 0x82828282u) - c8r;      // (n+2-8c) >= 0
        unsigned e2 = e1 - 0x08080808u;             // (n+2-8c) >= 8
        unsigned cm = (e1 & ~e2) & rm;
        tagpos  |= ((tm * 0x00204081u) >> 28) << (4 * w);
        candpos |= ((cm * 0x00204081u) >> 28) << (4 * w);
    }

    while (candpos) {
        int k = __ffs(candpos) - 1;
        candpos &= candpos - 1;
        unsigned nw = (k & 8) ? ((k & 4) ? N[3] : N[2])
                              : ((k & 4) ? N[1] : N[0]);
        unsigned u  = (prmt(nw, 0u, (unsigned)(k & 3)) & 0xFFu) - 22u;
        unsigned bit = 1u << u;
        unsigned tb = tagpos & ((2u << k) - 1u);    // in-batch tags at pos <= k
        if (tb) {
            int j = 31 - __clz(tb);
            unsigned pw = (j & 8) ? ((j & 4) ? P[3] : P[2])
                                  : ((j & 4) ? P[1] : P[0]);
            int tv = (int)(prmt(pw, 0u, (unsigned)(j & 3)) & 0xFFu) - 46;
            if (tv == qtag) mL |= bit;
        } else if (rtag >= 0) {
            if (rtag == qtag) mL |= bit;
        } else {
            mC |= bit;                              // pending: resolved by outer carry
        }
    }

    if (tagpos) {
        int j = 31 - __clz(tagpos);
        unsigned pw = (j & 8) ? ((j & 4) ? P[3] : P[2])
                              : ((j & 4) ? P[1] : P[0]);
        rtag = (int)(prmt(pw, 0u, (unsigned)(j & 3)) & 0xFFu) - 46;
    }
}

__global__ __launch_bounds__(TPB)
void tlc_kernel(const int* __restrict__ tok,
                const float* __restrict__ table,
                float* __restrict__ out)
{
    const int row  = blockIdx.x;
    const int* t   = tok + (size_t)row * SEQ;
    const int tid  = threadIdx.x;
    const int lane = tid & 31;
    const int wid  = tid >> 5;

    __shared__ alignas(16) unsigned sRaw[2][HALF];  // 2 x 8 KB TMA buffers
    __shared__ unsigned sTok[HALF / 4];             // 2 KB packed (reused per half)
    __shared__ alignas(8) unsigned long long mbar[2];
    __shared__ unsigned sM[NW], sP[NW];
    __shared__ int      sL[NW];

    const unsigned mb0 = smem_u32(&mbar[0]);
    const unsigned mb1 = smem_u32(&mbar[1]);

    if (tid == 0) {
        asm volatile("mbarrier.init.shared.b64 [%0], %1;" :: "r"(mb0), "r"(1) : "memory");
        asm volatile("mbarrier.init.shared.b64 [%0], %1;" :: "r"(mb1), "r"(1) : "memory");
    }
    __syncthreads();
    // both halves' copies issued up-front: >=1 outstanding at all times per CTA
    if (tid == 0) {
        #pragma unroll
        for (int k = 0; k < 2; k++) {
            unsigned mb = k ? mb1 : mb0;
            asm volatile("mbarrier.arrive.expect_tx.shared.b64 _, [%0], %1;"
                         :: "r"(mb), "r"((unsigned)(HALF * 4)) : "memory");
            asm volatile(
                "cp.async.bulk.shared::cluster.global.mbarrier::complete_tx::bytes "
                "[%0], [%1], %2, [%3];"
                :: "r"(smem_u32(sRaw[k])), "l"(t + k * HALF),
                   "r"((unsigned)(HALF * 4)), "r"(mb)
                : "memory");
        }
    }

    // uniform L2-broadcast loads while the TMAs fly
    const int qtag = min(max(__ldg(&t[SEQ - 1]) - 46, 0), 2);
    const int ttok = __ldg(&t[1]);

    int carry = -1;                  // row-running tag (thread 0 only)
    unsigned acc = 0;                // row-accumulated mask (thread 0 only)

    #pragma unroll
    for (int h = 0; h < 2; h++) {
        mbar_wait(h ? mb1 : mb0, 0u);

        // ---- restage: raw uint4 -> packed bytes, swizzled STS (conflict-free)
        const uint4* raw4 = reinterpret_cast<const uint4*>(sRaw[h]);
        #pragma unroll
        for (int i = 0; i < 4; i++) {
            uint4 v = raw4[i * TPB + tid];
            unsigned lo = prmt(v.x, v.y, 0x0040);
            unsigned hi = prmt(v.z, v.w, 0x4000);
            sTok[swz(i * TPB + tid)] = prmt(lo, hi, 0x7610);
        }
        __syncthreads();             // packed ready (also fences prior sM/sP reads)

        // ---- my 16 contiguous tokens of this half
        unsigned P[4];
        *reinterpret_cast<uint4*>(P) = *reinterpret_cast<const uint4*>(&sTok[swz(tid * 4)]);
        unsigned nfw;
        if (tid < TPB - 1)  nfw = sTok[swz(tid * 4 + 4)];
        else if (h == 0)    nfw = (unsigned)__ldg(&t[HALF]);   // half boundary
        else                nfw = 0u;                          // row-end sentinel

        int rtag = -1;
        unsigned mL = 0, mC = 0;
        batch16(P, nfw, qtag, rtag, mL, mC);

        // ---- warp inclusive scan of rtag: combine(a,b) = (b>=0 ? b : a)
        int inc = rtag;
        #pragma unroll
        for (int off = 1; off < 32; off <<= 1) {
            int p = __shfl_up_sync(0xffffffffu, inc, off);
            if (lane >= off && inc < 0) inc = p;
        }
        int excl = __shfl_up_sync(0xffffffffu, inc, 1);
        if (lane == 0) excl = -1;

        unsigned m    = mL | ((excl == qtag) ? mC : 0u);
        unsigned pend = (excl < 0) ? mC : 0u;
        m    = __reduce_or_sync(0xffffffffu, m);
        pend = __reduce_or_sync(0xffffffffu, pend);
        const int wlast = __shfl_sync(0xffffffffu, inc, 31);

        if (lane == 0) { sM[wid] = m; sP[wid] = pend; sL[wid] = wlast; }
        __syncthreads();

        // ---- cross-warp resolve for this half; thread 0 carries the row state
        if (tid < NW) {
            unsigned mm = sM[tid], pp = sP[tid];
            int c2 = sL[tid];
            #pragma unroll
            for (int off = 1; off < NW; off <<= 1) {
                int p = __shfl_up_sync(0xfu, c2, off);
                if (tid >= off && c2 < 0) c2 = p;
            }
            int ex = __shfl_up_sync(0xfu, c2, 1);
            if (tid == 0) ex = -1;
            unsigned res   = mm | ((ex == qtag) ? pp : 0u);
            unsigned pendh = (ex < 0) ? pp : 0u;          // needs row carry
            res   = __reduce_or_sync(0xfu, res);
            pendh = __reduce_or_sync(0xfu, pendh);
            const int halfLast = __shfl_sync(0xfu, c2, NW - 1);

            if (tid == 0) {
                acc |= res | ((carry == qtag) ? pendh : 0u);
                if (halfLast >= 0) carry = halfLast;
            }
        }
    }

    // ---- epilogue (thread 0)
    if (tid == 0) {
        unsigned mA  =  acc        & 0xffu;
        unsigned mB  = (acc >> 8)  & 0xffu;
        unsigned mCm = (acc >> 16) & 0xffu;
        const int a = mA  ? (__ffs(mA)  - 1) : 0;
        const int b = mB  ? (__ffs(mB)  - 1) : 0;
        const int c = mCm ? (__ffs(mCm) - 1) : 0;

        const int task = min(max(ttok - 49, 0), 3);

        float o[8];
        if (task == 3) {
            const float* tp = table + (((a * 8 + b) * 8 + c) * 8);
            #pragma unroll
            for (int k = 0; k < 8; k++) o[k] = __ldg(&tp[k]);
        } else {
            int idx;
            if (task == 0)      idx = a;
            else if (task == 1) idx = (a + 2 * b + 3 * c) & 7;
            else                idx = (a * (b + 1) + c * ((a ^ b) + 1)) & 7;
            #pragma unroll
            for (int k = 0; k < 8; k++) o[k] = (k == idx) ? 12.0f : 0.0f;
        }

        float4* o4 = reinterpret_cast<float4*>(out + (size_t)row * 8);
        o4[0] = make_float4(o[0], o[1], o[2], o[3]);
        o4[1] = make_float4(o[4], o[5], o[6], o[7]);
    }
}

extern "C" void kernel_launch(void* const* d_in, const int* in_sizes, int n_in,
                              void* d_out, int out_size)
{
    const int* tok     = (const int*)d_in[0];     // token_ids [B, 4096] int32
    const float* table = (const float*)d_in[1];   // lookup_table [8,8,8,8] f32
    float* out         = (float*)d_out;           // [B, 8] f32

    const int B = in_sizes[0] / SEQ;
    tlc_kernel<<<B, TPB>>>(tok, table, out);
}

// round 13
// speedup vs baseline: 1.3479x; 1.1854x over previous
#include <cuda_runtime.h>

#define SEQ 4096
#define TPB 256
#define NW (TPB / 32)

__device__ __forceinline__ unsigned prmt(unsigned a, unsigned b, unsigned sel) {
    unsigned r;
    asm("prmt.b32 %0, %1, %2, %3;" : "=r"(r) : "r"(a), "r"(b), "r"(sel));
    return r;
}

__global__ __launch_bounds__(TPB)
void tlc_kernel(const int* __restrict__ tok,
                const float* __restrict__ table,
                float* __restrict__ out)
{
    const int row  = blockIdx.x;
    const int* t   = tok + (size_t)row * SEQ;
    const int tid  = threadIdx.x;
    const int lane = tid & 31;
    const int wid  = tid >> 5;

    __shared__ unsigned sTok[SEQ / 4];          // whole row, byte-packed (4 KB)
    __shared__ unsigned sM[NW], sP[NW];
    __shared__ int      sL[NW];

    // ---- coalesced staging with 256-bit loads: 2 x LDG.256 per thread.
    // segment = 8 consecutive int32 tokens (32B); lane-consecutive segments ->
    // each warp LDG.256 covers 1024B contiguous (8 lines, minimal).
    const unsigned* g = reinterpret_cast<const unsigned*>(t);
    #pragma unroll
    for (int i = 0; i < 2; i++) {
        const int s = i * TPB + tid;            // segment index 0..511
        unsigned a0, a1, a2, a3, a4, a5, a6, a7;
        asm("ld.global.v8.b32 {%0,%1,%2,%3,%4,%5,%6,%7}, [%8];"
            : "=r"(a0), "=r"(a1), "=r"(a2), "=r"(a3),
              "=r"(a4), "=r"(a5), "=r"(a6), "=r"(a7)
            : "l"(g + 8 * s));
        unsigned lo0 = prmt(a0, a1, 0x0040), hi0 = prmt(a2, a3, 0x4000);
        unsigned lo1 = prmt(a4, a5, 0x0040), hi1 = prmt(a6, a7, 0x4000);
        uint2 w;
        w.x = prmt(lo0, hi0, 0x7610);
        w.y = prmt(lo1, hi1, 0x7610);
        *reinterpret_cast<uint2*>(&sTok[2 * s]) = w;   // STS.64, conflict-free
    }
    __syncthreads();

    // thread's contiguous 16 tokens as 4 packed words (conflict-free LDS.128)
    unsigned P[4];
    *reinterpret_cast<uint4*>(P) = *reinterpret_cast<const uint4*>(&sTok[tid * 4]);

    // query tag: last token of row = byte3 of last packed word (broadcast LDS)
    const int qtag = min(max((int)(sTok[SEQ / 4 - 1] >> 24) - 46, 0), 2);

    // next chunk's first packed word (byte0 = boundary token); sentinel 0 at row end
    unsigned nfw = __shfl_down_sync(0xffffffffu, P[0], 1);
    if (lane == 31) nfw = (tid == TPB - 1) ? 0u : sTok[tid * 4 + 4];

    unsigned N[4];
    N[0] = prmt(P[0], P[1], 0x4321);
    N[1] = prmt(P[1], P[2], 0x4321);
    N[2] = prmt(P[2], P[3], 0x4321);
    N[3] = prmt(P[3], nfw,  0x4321);

    // ---- SWAR detection: per-byte bit7 flags, movemask to 16-bit position masks.
    // Valid because all token bytes < 128 (no cross-byte carries/borrows).
    unsigned tagpos = 0, candpos = 0;
    #pragma unroll
    for (int w = 0; w < 4; w++) {
        unsigned p = P[w], n = N[w];
        unsigned d1 = p + 0x52525252u;          // tag: (c-46) <u 3
        unsigned d2 = d1 - 0x03030303u;
        unsigned tm = (d1 & ~d2) & 0x80808080u;
        unsigned r1 = p + 0x7D7D7D7Du;          // role: (c-3) <u 3
        unsigned r2 = r1 - 0x03030303u;
        unsigned rm = (r1 & ~r2) & 0x80808080u;
        unsigned c8  = (p << 3) & 0xF8F8F8F8u;
        unsigned c8r = c8 & ((rm >> 7) * 0xF8u);    // mask junk-byte borrows
        unsigned e1 = (n + 0x82828282u) - c8r;      // (n+2-8c) >= 0
        unsigned e2 = e1 - 0x08080808u;             // (n+2-8c) >= 8
        unsigned cm = (e1 & ~e2) & rm;
        tagpos  |= ((tm * 0x00204081u) >> 28) << (4 * w);
        candpos |= ((cm * 0x00204081u) >> 28) << (4 * w);
    }

    // ---- chunk lastTag from msb of tagpos
    int lastTag = -1;
    if (tagpos) {
        int j = 31 - __clz(tagpos);
        unsigned pw = (j & 8) ? ((j & 4) ? P[3] : P[2])
                              : ((j & 4) ? P[1] : P[0]);
        lastTag = (int)(prmt(pw, 0u, (unsigned)(j & 3)) & 0xFFu) - 46;
    }

    // ---- rare path: resolve each candidate's governing tag
    unsigned mL = 0, mC = 0;
    while (candpos) {
        int k = __ffs(candpos) - 1;
        candpos &= candpos - 1;
        unsigned nw = (k & 8) ? ((k & 4) ? N[3] : N[2])
                              : ((k & 4) ? N[1] : N[0]);
        unsigned u  = (prmt(nw, 0u, (unsigned)(k & 3)) & 0xFFu) - 22u;  // bit 0..23
        unsigned bit = 1u << u;
        unsigned tb = tagpos & ((2u << k) - 1u);    // in-thread tags at pos <= k
        if (tb) {
            int j = 31 - __clz(tb);
            unsigned pw = (j & 8) ? ((j & 4) ? P[3] : P[2])
                                  : ((j & 4) ? P[1] : P[0]);
            int tv = (int)(prmt(pw, 0u, (unsigned)(j & 3)) & 0xFFu) - 46;
            if (tv == qtag) mL |= bit;
        } else {
            mC |= bit;                              // governed by carry tag
        }
    }

    // ---- warp inclusive scan of lastTag: combine(a,b) = (b>=0 ? b : a)
    int inc = lastTag;
    #pragma unroll
    for (int off = 1; off < 32; off <<= 1) {
        int p = __shfl_up_sync(0xffffffffu, inc, off);
        if (lane >= off && inc < 0) inc = p;
    }
    int excl = __shfl_up_sync(0xffffffffu, inc, 1);
    if (lane == 0) excl = -1;

    unsigned m    = mL | ((excl == qtag) ? mC : 0u);
    unsigned pend = (excl < 0) ? mC : 0u;

    m    = __reduce_or_sync(0xffffffffu, m);
    pend = __reduce_or_sync(0xffffffffu, pend);
    const int wlast = __shfl_sync(0xffffffffu, inc, 31);

    if (lane == 0) { sM[wid] = m; sP[wid] = pend; sL[wid] = wlast; }
    __syncthreads();

    // ---- cross-warp resolve + epilogue (8 threads of warp 0)
    if (tid < NW) {
        unsigned mm = sM[tid], pp = sP[tid];
        int c2 = sL[tid];
        #pragma unroll
        for (int off = 1; off < NW; off <<= 1) {
            int p = __shfl_up_sync(0xffu, c2, off);
            if (tid >= off && c2 < 0) c2 = p;
        }
        int ex = __shfl_up_sync(0xffu, c2, 1);
        if (tid == 0) ex = -1;
        unsigned res = mm | ((ex == qtag) ? pp : 0u);
        res = __reduce_or_sync(0xffu, res);

        if (tid == 0) {
            unsigned mA  =  res        & 0xffu;
            unsigned mB  = (res >> 8)  & 0xffu;
            unsigned mCm = (res >> 16) & 0xffu;
            const int a = mA  ? (__ffs(mA)  - 1) : 0;
            const int b = mB  ? (__ffs(mB)  - 1) : 0;
            const int c = mCm ? (__ffs(mCm) - 1) : 0;

            const int task = min(max((int)((sTok[0] >> 8) & 0xFFu) - 49, 0), 3);

            float o[8];
            if (task == 3) {
                const float* tp = table + (((a * 8 + b) * 8 + c) * 8);
                #pragma unroll
                for (int k = 0; k < 8; k++) o[k] = __ldg(&tp[k]);
            } else {
                int idx;
                if (task == 0)      idx = a;
                else if (task == 1) idx = (a + 2 * b + 3 * c) & 7;
                else                idx = (a * (b + 1) + c * ((a ^ b) + 1)) & 7;
                #pragma unroll
                for (int k = 0; k < 8; k++) o[k] = (k == idx) ? 12.0f : 0.0f;
            }

            float4* o4 = reinterpret_cast<float4*>(out + (size_t)row * 8);
            o4[0] = make_float4(o[0], o[1], o[2], o[3]);
            o4[1] = make_float4(o[4], o[5], o[6], o[7]);
        }
    }
}

extern "C" void kernel_launch(void* const* d_in, const int* in_sizes, int n_in,
                              void* d_out, int out_size)
{
    const int* tok     = (const int*)d_in[0];     // token_ids [B, 4096] int32
    const float* table = (const float*)d_in[1];   // lookup_table [8,8,8,8] f32
    float* out         = (float*)d_out;           // [B, 8] f32

    const int B = in_sizes[0] / SEQ;
    tlc_kernel<<<B, TPB>>>(tok, table, out);
}